// round 16
// baseline (speedup 1.0000x reference)
#include <cuda_runtime.h>
#include <cuda_bf16.h>
#include <math.h>
#include <stdint.h>

// Problem constants
#define BATCH   2
#define LSEQ    2048
#define DMODEL  1024
#define DINNER  2048
#define NSTATE  16
#define KCONV   4
#define MTOT    (BATCH * LSEQ)      // 4096

// ---------------------------------------------------------------------------
// Static scratch
// ---------------------------------------------------------------------------
__device__ float g_xz[MTOT * DINNER];
__device__ float g_xg[MTOT * DINNER];
__device__ float g_act[MTOT * DINNER];
__device__ float g_delta[MTOT * DINNER];
__device__ float g_Bm[MTOT * NSTATE];
__device__ float g_Cm[MTOT * NSTATE];

// tf32-rounded fp32 GEMM operands
__device__ float g_xt[MTOT * DMODEL];            // rounded x
__device__ float g_at[MTOT * DINNER];            // rounded act
__device__ float g_gt[MTOT * DINNER];            // rounded gated
__device__ float g_wt_ing[2 * DINNER * DMODEL];  // [4096][1024]  in|gate transposed
__device__ float g_wtd[DINNER * DINNER];         // [2048][2048]  delta transposed
__device__ float g_wto[DMODEL * DINNER];         // [1024][2048]  out transposed

// ---------------------------------------------------------------------------
// PTX helpers
// ---------------------------------------------------------------------------
__device__ __forceinline__ uint32_t smem_u32(const void* p) {
    uint32_t a;
    asm("{ .reg .u64 t; cvta.to.shared.u64 t, %1; cvt.u32.u64 %0, t; }"
        : "=r"(a) : "l"(p));
    return a;
}
__device__ __forceinline__ void cpa16(uint32_t dst, const void* src) {
    asm volatile("cp.async.cg.shared.global [%0], [%1], 16;"
                 :: "r"(dst), "l"(src));
}
__device__ __forceinline__ uint32_t lds32(uint32_t addr) {
    uint32_t v;
    asm volatile("ld.shared.b32 %0, [%1];" : "=r"(v) : "r"(addr));
    return v;
}
__device__ __forceinline__ float to_tf32(float f) {
    uint32_t o, i = __float_as_uint(f);
    asm("cvt.rna.tf32.f32 %0, %1;" : "=r"(o) : "r"(i));
    return __uint_as_float(o);
}
__device__ __forceinline__ void mma_tf32(float* d, const uint32_t* a,
                                         uint32_t b0, uint32_t b1) {
    asm volatile(
        "mma.sync.aligned.m16n8k8.row.col.f32.tf32.tf32.f32 "
        "{%0,%1,%2,%3}, {%4,%5,%6,%7}, {%8,%9}, {%0,%1,%2,%3};"
        : "+f"(d[0]), "+f"(d[1]), "+f"(d[2]), "+f"(d[3])
        : "r"(a[0]), "r"(a[1]), "r"(a[2]), "r"(a[3]), "r"(b0), "r"(b1));
}

// ---------------------------------------------------------------------------
// tf32 mma.sync GEMM (identical to R13/R15 — proven)
// ---------------------------------------------------------------------------
#define MG_STAGE  16384        // A(8K) + B(8K)

__device__ __forceinline__ void load_stage(uint32_t sstage,
        const float* __restrict__ A, const float* __restrict__ B,
        int arow0, int brow0, int K, int kc, int tid)
{
#pragma unroll
    for (int it = 0; it < 2; it++) {
        const int idx = tid + 256 * it;      // 0..511
        const int rr  = idx >> 2;            // row 0..127
        const int c4  = idx & 3;             // 16B chunk
        const uint32_t soff = rr * 64 + ((c4 ^ ((rr >> 1) & 3)) << 4);
        cpa16(sstage +        soff, A + (size_t)(arow0 + rr) * K + kc + c4 * 4);
        cpa16(sstage + 8192 + soff, B + (size_t)(brow0 + rr) * K + kc + c4 * 4);
    }
}

template<int EPI>   // 0: bias, 1: bias + softplus
__global__ __launch_bounds__(256, 2)
void mmagemm(const float* __restrict__ A, const float* __restrict__ B,
             const float* __restrict__ bias0, const float* __restrict__ bias1,
             float* __restrict__ C0, float* __restrict__ C1,
             int Nout, int Nsplit, int K)
{
    __shared__ char smem[3 * MG_STAGE];     // 48 KB static
    const uint32_t sb = smem_u32(smem);
    const int tid  = threadIdx.x;
    const int wid  = tid >> 5;
    const int lane = tid & 31;
    const int warp_m = wid & 1;
    const int warp_n = wid >> 1;
    const int arow0 = blockIdx.y * 128;
    const int brow0 = blockIdx.x * 128;

    const int rA = lane >> 2;                 // 0..7
    const int cA = lane & 3;                  // 0..3
    const int swz = ((rA >> 1) & 3) << 2;
    uint32_t kx[2], kx4[2];
#pragma unroll
    for (int s = 0; s < 2; s++) {
        kx[s]  = (uint32_t)(((s * 8 + cA)     ^ swz) << 2);
        kx4[s] = (uint32_t)(((s * 8 + cA + 4) ^ swz) << 2);
    }
    const int m0 = warp_m * 64;
    const int n0 = warp_n * 32;

    float acc[4][4][4];
#pragma unroll
    for (int a = 0; a < 4; a++)
#pragma unroll
        for (int b = 0; b < 4; b++)
#pragma unroll
            for (int c = 0; c < 4; c++) acc[a][b][c] = 0.f;

    const int nch = K >> 4;

    load_stage(sb,            A, B, arow0, brow0, K, 0,  tid);
    asm volatile("cp.async.commit_group;");
    load_stage(sb + MG_STAGE, A, B, arow0, brow0, K, 16, tid);
    asm volatile("cp.async.commit_group;");

    int stage = 0;
    for (int i = 0; i < nch; i++) {
        if (i + 1 < nch) {
            asm volatile("cp.async.wait_group 1;");
        } else {
            asm volatile("cp.async.wait_group 0;");
        }
        __syncthreads();

        if (i + 2 < nch) {
            int ns = stage + 2; if (ns >= 3) ns -= 3;
            load_stage(sb + ns * MG_STAGE, A, B, arow0, brow0, K, (i + 2) * 16, tid);
            asm volatile("cp.async.commit_group;");
        }

        const uint32_t st = sb + stage * MG_STAGE;
#pragma unroll
        for (int ks = 0; ks < 2; ks++) {
            uint32_t bf[4][2];
#pragma unroll
            for (int nt = 0; nt < 4; nt++) {
                const uint32_t rb = st + 8192 + (n0 + nt * 8 + rA) * 64;
                bf[nt][0] = lds32(rb + kx[ks]);
                bf[nt][1] = lds32(rb + kx4[ks]);
            }
#pragma unroll
            for (int mt = 0; mt < 4; mt++) {
                const uint32_t ra = st + (m0 + mt * 16 + rA) * 64;
                uint32_t af[4];
                af[0] = lds32(ra +       kx[ks]);
                af[1] = lds32(ra + 512 + kx[ks]);
                af[2] = lds32(ra +       kx4[ks]);
                af[3] = lds32(ra + 512 + kx4[ks]);
#pragma unroll
                for (int nt = 0; nt < 4; nt++)
                    mma_tf32(acc[mt][nt], af, bf[nt][0], bf[nt][1]);
            }
        }
        if (++stage == 3) stage = 0;
    }

    const float* bias = bias0;
    float* Cp = C0;
    int colbase = brow0;
    if (brow0 >= Nsplit) { bias = bias1; Cp = C1; colbase = brow0 - Nsplit; }

    const int gid = lane >> 2, tig = lane & 3;
#pragma unroll
    for (int mt = 0; mt < 4; mt++) {
        const int r0 = arow0 + m0 + mt * 16 + gid;
#pragma unroll
        for (int nt = 0; nt < 4; nt++) {
            const int col = colbase + n0 + nt * 8 + tig * 2;
            const float bb0 = __ldg(bias + col);
            const float bb1 = __ldg(bias + col + 1);
            float v0 = acc[mt][nt][0] + bb0;
            float v1 = acc[mt][nt][1] + bb1;
            float v2 = acc[mt][nt][2] + bb0;
            float v3 = acc[mt][nt][3] + bb1;
            if (EPI == 1) {
                v0 = (v0 > 20.f) ? v0 : log1pf(expf(v0));
                v1 = (v1 > 20.f) ? v1 : log1pf(expf(v1));
                v2 = (v2 > 20.f) ? v2 : log1pf(expf(v2));
                v3 = (v3 > 20.f) ? v3 : log1pf(expf(v3));
            }
            float2 p01; p01.x = v0; p01.y = v1;
            float2 p23; p23.x = v2; p23.y = v3;
            *(float2*)(Cp + (size_t)r0 * Nout + col)       = p01;
            *(float2*)(Cp + (size_t)(r0 + 8) * Nout + col) = p23;
        }
    }
}

// ---------------------------------------------------------------------------
// Prep kernel: x->tf32 round PLUS all 4 weight transposes, one launch.
// Block ranges: [0,4096) round, then in/gate/delta/out transpose tiles.
// ---------------------------------------------------------------------------
__device__ __forceinline__ void tr_tile(const float* __restrict__ W, int K, int N,
                                        float* __restrict__ T, int nt, int kt,
                                        int tid)
{
    __shared__ float ts[32][33];
    const int n0 = nt * 32, k0 = kt * 32;
    const int tx = tid & 31, ty = tid >> 5;
#pragma unroll
    for (int i = 0; i < 4; i++)
        ts[ty + i * 8][tx] = W[(size_t)(k0 + ty + i * 8) * N + n0 + tx];
    __syncthreads();
#pragma unroll
    for (int i = 0; i < 4; i++)
        T[(size_t)(n0 + ty + i * 8) * K + k0 + tx] = to_tf32(ts[tx][ty + i * 8]);
}

#define NB_ROUND 4096      // (MTOT*DMODEL/4)/256
#define NB_IN    2048      // 64 x 32 tiles
#define NB_GATE  2048
#define NB_DELTA 4096      // 64 x 64
#define NB_OUT   2048      // 32 x 64
#define NB_PREP  (NB_ROUND + NB_IN + NB_GATE + NB_DELTA + NB_OUT)

__global__ __launch_bounds__(256)
void prep_kernel(const float* __restrict__ x,
                 const float* __restrict__ W_in, const float* __restrict__ W_gate,
                 const float* __restrict__ W_delta, const float* __restrict__ W_out,
                 float* __restrict__ xt, float* __restrict__ wt_ing,
                 float* __restrict__ wtd, float* __restrict__ wto)
{
    const int tid = threadIdx.x;
    int b = blockIdx.x;
    if (b < NB_ROUND) {
        const int i = b * 256 + tid;
        float4 v = ((const float4*)x)[i];
        v.x = to_tf32(v.x); v.y = to_tf32(v.y);
        v.z = to_tf32(v.z); v.w = to_tf32(v.w);
        ((float4*)xt)[i] = v;
        return;
    }
    b -= NB_ROUND;
    if (b < NB_IN) {
        tr_tile(W_in, DMODEL, DINNER, wt_ing, b & 63, b >> 6, tid);
        return;
    }
    b -= NB_IN;
    if (b < NB_GATE) {
        tr_tile(W_gate, DMODEL, DINNER, wt_ing + (size_t)DINNER * DMODEL,
                b & 63, b >> 6, tid);
        return;
    }
    b -= NB_GATE;
    if (b < NB_DELTA) {
        tr_tile(W_delta, DINNER, DINNER, wtd, b & 63, b >> 6, tid);
        return;
    }
    b -= NB_DELTA;
    tr_tile(W_out, DINNER, DMODEL, wto, b & 31, b >> 5, tid);
}

// ---------------------------------------------------------------------------
// Causal depthwise conv (K=4) + bias + silu, float4 over channels.
// Same per-element arithmetic order as scalar version.
// ---------------------------------------------------------------------------
__global__ __launch_bounds__(256)
void conv_silu(const float* __restrict__ xz, const float* __restrict__ w,
               const float* __restrict__ cb, float* __restrict__ act,
               float* __restrict__ act_t)
{
    const int i4 = blockIdx.x * 256 + threadIdx.x;   // over MTOT*DINNER/4
    if (i4 >= MTOT * DINNER / 4) return;
    const int idx = i4 * 4;
    const int d = idx & (DINNER - 1);                // multiple of 4
    const int bt = idx >> 11;
    const int t = bt & (LSEQ - 1);

    // weights for 4 channels: wv[j] = w[(d+j)*4 + 0..3]
    float4 wv0 = *(const float4*)(w + (d + 0) * KCONV);
    float4 wv1 = *(const float4*)(w + (d + 1) * KCONV);
    float4 wv2 = *(const float4*)(w + (d + 2) * KCONV);
    float4 wv3 = *(const float4*)(w + (d + 3) * KCONV);
    float4 s = *(const float4*)(cb + d);

#pragma unroll
    for (int k = 0; k < KCONV; k++) {
        const int tt = t - (KCONV - 1) + k;
        if (tt >= 0) {
            const float4 v = *(const float4*)(xz + idx + (k - (KCONV - 1)) * DINNER);
            const float w0 = (k == 0) ? wv0.x : (k == 1) ? wv0.y : (k == 2) ? wv0.z : wv0.w;
            const float w1 = (k == 0) ? wv1.x : (k == 1) ? wv1.y : (k == 2) ? wv1.z : wv1.w;
            const float w2 = (k == 0) ? wv2.x : (k == 1) ? wv2.y : (k == 2) ? wv2.z : wv2.w;
            const float w3 = (k == 0) ? wv3.x : (k == 1) ? wv3.y : (k == 2) ? wv3.z : wv3.w;
            s.x = fmaf(w0, v.x, s.x);
            s.y = fmaf(w1, v.y, s.y);
            s.z = fmaf(w2, v.z, s.z);
            s.w = fmaf(w3, v.w, s.w);
        }
    }
    float4 a4, t4;
    a4.x = s.x / (1.f + __expf(-s.x));
    a4.y = s.y / (1.f + __expf(-s.y));
    a4.z = s.z / (1.f + __expf(-s.z));
    a4.w = s.w / (1.f + __expf(-s.w));
    t4.x = to_tf32(a4.x); t4.y = to_tf32(a4.y);
    t4.z = to_tf32(a4.z); t4.w = to_tf32(a4.w);
    *(float4*)(act + idx)   = a4;
    *(float4*)(act_t + idx) = t4;
}

// ---------------------------------------------------------------------------
// Skinny GEMM: Bm = act @ W_B, Cm = act @ W_C  — float4 n-quads.
// One thread per (m, n-quad); k ascending, single accumulator per (m,n)
// -> bitwise-identical to the scalar version.
// ---------------------------------------------------------------------------
__global__ __launch_bounds__(256)
void bc_gemm(const float* __restrict__ act,
             const float* __restrict__ WB, const float* __restrict__ WC,
             float* __restrict__ Bm, float* __restrict__ Cm)
{
    const int g = blockIdx.x * 256 + threadIdx.x;   // 0..16383
    const int m = g >> 2;
    const int q = (g & 3) * 4;
    const float* a = act + (size_t)m * DINNER;

    float4 sb = make_float4(0.f, 0.f, 0.f, 0.f);
    float4 sc = make_float4(0.f, 0.f, 0.f, 0.f);
#pragma unroll 8
    for (int k = 0; k < DINNER; k++) {
        const float av = a[k];
        const float4 wb = *(const float4*)(WB + k * NSTATE + q);
        const float4 wc = *(const float4*)(WC + k * NSTATE + q);
        sb.x = fmaf(av, wb.x, sb.x);
        sb.y = fmaf(av, wb.y, sb.y);
        sb.z = fmaf(av, wb.z, sb.z);
        sb.w = fmaf(av, wb.w, sb.w);
        sc.x = fmaf(av, wc.x, sc.x);
        sc.y = fmaf(av, wc.y, sc.y);
        sc.z = fmaf(av, wc.z, sc.z);
        sc.w = fmaf(av, wc.w, sc.w);
    }
    *(float4*)(Bm + m * NSTATE + q) = sb;
    *(float4*)(Cm + m * NSTATE + q) = sc;
}

// ---------------------------------------------------------------------------
// Selective scan + skip + gating (R15 structure — proven).
// ---------------------------------------------------------------------------
__global__ __launch_bounds__(256)
void scan_kernel(const float* __restrict__ delta, const float* __restrict__ act,
                 const float* __restrict__ Bm, const float* __restrict__ Cm,
                 const float* __restrict__ A_log, const float* __restrict__ D_skip,
                 const float* __restrict__ xg, float* __restrict__ gt)
{
    const int w = blockIdx.x * 8 + (threadIdx.x >> 5);   // 0 .. 2047
    const int lane = threadIdx.x & 31;
    const int n = lane & 15;
    const int b = w >> 10;
    const int dp = w & 1023;
    const int d = dp * 2 + (lane >> 4);

    const float a = -expf(A_log[d * NSTATE + n]);
    const float dsk = D_skip[d];

    const float* pD = delta + (size_t)b * LSEQ * DINNER + d;
    const float* pX = act   + (size_t)b * LSEQ * DINNER + d;
    const float* pG = xg    + (size_t)b * LSEQ * DINNER + d;
    float*       pT = gt    + (size_t)b * LSEQ * DINNER + d;
    const float* pB = Bm + (size_t)b * LSEQ * NSTATE + n;
    const float* pC = Cm + (size_t)b * LSEQ * NSTATE + n;

    float h = 0.f;
    for (int t0 = 0; t0 < LSEQ; t0 += 8) {
        float dv[8], xv[8], gv[8], bv[8], cv[8];
#pragma unroll
        for (int jj = 0; jj < 8; jj++) {
            const size_t o = (size_t)(t0 + jj) * DINNER;
            dv[jj] = pD[o];
            xv[jj] = pX[o];
            gv[jj] = pG[o];
            bv[jj] = pB[(t0 + jj) * NSTATE];
            cv[jj] = pC[(t0 + jj) * NSTATE];
        }
        float dA[8];
#pragma unroll
        for (int jj = 0; jj < 8; jj++) dA[jj] = __expf(dv[jj] * a);
        float p[8];
#pragma unroll
        for (int jj = 0; jj < 8; jj++) {
            h = fmaf(dA[jj], h, (dv[jj] * xv[jj]) * bv[jj]);
            p[jj] = h * cv[jj];
        }
#pragma unroll
        for (int s = 1; s <= 8; s <<= 1) {
#pragma unroll
            for (int jj = 0; jj < 8; jj++)
                p[jj] += __shfl_xor_sync(0xffffffffu, p[jj], s);
        }
        if (n == 0) {
#pragma unroll
            for (int jj = 0; jj < 8; jj++) {
                const float g = gv[jj];
                const float y = (p[jj] + xv[jj] * dsk) * (g / (1.f + __expf(-g)));
                pT[(size_t)(t0 + jj) * DINNER] = to_tf32(y);
            }
        }
    }
}

// ---------------------------------------------------------------------------
// Launch
// ---------------------------------------------------------------------------
extern "C" void kernel_launch(void* const* d_in, const int* in_sizes, int n_in,
                              void* d_out, int out_size)
{
    const float* x      = (const float*)d_in[0];
    const float* W_in   = (const float*)d_in[1];
    const float* b_in   = (const float*)d_in[2];
    const float* W_gate = (const float*)d_in[3];
    const float* b_gate = (const float*)d_in[4];
    const float* conv_w = (const float*)d_in[5];
    const float* conv_b = (const float*)d_in[6];
    const float* A_log  = (const float*)d_in[7];
    const float* D_skip = (const float*)d_in[8];
    const float* W_delta= (const float*)d_in[9];
    const float* b_delta= (const float*)d_in[10];
    const float* W_B    = (const float*)d_in[11];
    const float* W_C    = (const float*)d_in[12];
    const float* W_out  = (const float*)d_in[13];
    const float* b_out  = (const float*)d_in[14];
    float* out = (float*)d_out;

    float *xz, *xg, *act, *delt, *Bm, *Cm, *xt, *at, *gt, *wt_ing, *wtd, *wto;
    cudaGetSymbolAddress((void**)&xz,     g_xz);
    cudaGetSymbolAddress((void**)&xg,     g_xg);
    cudaGetSymbolAddress((void**)&act,    g_act);
    cudaGetSymbolAddress((void**)&delt,   g_delta);
    cudaGetSymbolAddress((void**)&Bm,     g_Bm);
    cudaGetSymbolAddress((void**)&Cm,     g_Cm);
    cudaGetSymbolAddress((void**)&xt,     g_xt);
    cudaGetSymbolAddress((void**)&at,     g_at);
    cudaGetSymbolAddress((void**)&gt,     g_gt);
    cudaGetSymbolAddress((void**)&wt_ing, g_wt_ing);
    cudaGetSymbolAddress((void**)&wtd,    g_wtd);
    cudaGetSymbolAddress((void**)&wto,    g_wto);

    // 0) one prep launch: round x + transpose/round all 4 weight matrices
    prep_kernel<<<NB_PREP, 256>>>(x, W_in, W_gate, W_delta, W_out,
                                  xt, wt_ing, wtd, wto);
    // 1) fused in+gate: [xz | xg] = x @ [W_in | W_gate] + [b_in | b_gate]
    {
        dim3 grid(2 * DINNER / 128, MTOT / 128);     // 32 x 32
        mmagemm<0><<<grid, 256>>>(xt, wt_ing, b_in, b_gate,
                                  xz, xg, DINNER, DINNER, DMODEL);
    }
    // 2) act = silu(conv(xz) + conv_b)  (+ tf32 copy)
    {
        const int n4 = MTOT * DINNER / 4;
        conv_silu<<<(n4 + 255) / 256, 256>>>(xz, conv_w, conv_b, act, at);
    }
    // 3) delta = softplus(act @ W_delta + b_delta)
    {
        dim3 grid(DINNER / 128, MTOT / 128);
        mmagemm<1><<<grid, 256>>>(at, wtd, b_delta, b_delta,
                                  delt, delt, DINNER, DINNER, DINNER);
    }
    // 4) Bm, Cm
    {
        bc_gemm<<<MTOT * 4 / 256, 256>>>(act, W_B, W_C, Bm, Cm);
    }
    // 5) scan + skip + gating -> gt (tf32-rounded)
    {
        scan_kernel<<<(BATCH * DINNER / 2) / 8, 256>>>(delt, act, Bm, Cm,
                                                       A_log, D_skip, xg, gt);
    }
    // 6) out = gated @ W_out + b_out
    {
        dim3 grid(DMODEL / 128, MTOT / 128);
        mmagemm<0><<<grid, 256>>>(gt, wto, b_out, b_out,
                                  out, out, DMODEL, DMODEL, DINNER);
    }
}

// round 17
// speedup vs baseline: 1.0114x; 1.0114x over previous
#include <cuda_runtime.h>
#include <cuda_bf16.h>
#include <math.h>
#include <stdint.h>

// Problem constants
#define BATCH   2
#define LSEQ    2048
#define DMODEL  1024
#define DINNER  2048
#define NSTATE  16
#define KCONV   4
#define MTOT    (BATCH * LSEQ)      // 4096

// ---------------------------------------------------------------------------
// Static scratch
// ---------------------------------------------------------------------------
__device__ float g_xz[MTOT * DINNER];
__device__ float g_xg[MTOT * DINNER];
__device__ float g_act[MTOT * DINNER];
__device__ float g_delta[MTOT * DINNER];
__device__ float g_Bm[MTOT * NSTATE];
__device__ float g_Cm[MTOT * NSTATE];

// tf32-rounded fp32 GEMM operands
__device__ float g_xt[MTOT * DMODEL];            // rounded x
__device__ float g_at[MTOT * DINNER];            // rounded act
__device__ float g_gt[MTOT * DINNER];            // rounded gated
__device__ float g_wt_ing[2 * DINNER * DMODEL];  // [4096][1024]  in|gate transposed
__device__ float g_wtd[DINNER * DINNER];         // [2048][2048]  delta transposed
__device__ float g_wto[DMODEL * DINNER];         // [1024][2048]  out transposed

// ---------------------------------------------------------------------------
// PTX helpers
// ---------------------------------------------------------------------------
__device__ __forceinline__ uint32_t smem_u32(const void* p) {
    uint32_t a;
    asm("{ .reg .u64 t; cvta.to.shared.u64 t, %1; cvt.u32.u64 %0, t; }"
        : "=r"(a) : "l"(p));
    return a;
}
__device__ __forceinline__ void cpa16(uint32_t dst, const void* src) {
    asm volatile("cp.async.cg.shared.global [%0], [%1], 16;"
                 :: "r"(dst), "l"(src));
}
__device__ __forceinline__ uint32_t lds32(uint32_t addr) {
    uint32_t v;
    asm volatile("ld.shared.b32 %0, [%1];" : "=r"(v) : "r"(addr));
    return v;
}
__device__ __forceinline__ float to_tf32(float f) {
    uint32_t o, i = __float_as_uint(f);
    asm("cvt.rna.tf32.f32 %0, %1;" : "=r"(o) : "r"(i));
    return __uint_as_float(o);
}
__device__ __forceinline__ void mma_tf32(float* d, const uint32_t* a,
                                         uint32_t b0, uint32_t b1) {
    asm volatile(
        "mma.sync.aligned.m16n8k8.row.col.f32.tf32.tf32.f32 "
        "{%0,%1,%2,%3}, {%4,%5,%6,%7}, {%8,%9}, {%0,%1,%2,%3};"
        : "+f"(d[0]), "+f"(d[1]), "+f"(d[2]), "+f"(d[3])
        : "r"(a[0]), "r"(a[1]), "r"(a[2]), "r"(a[3]), "r"(b0), "r"(b1));
}

// ---------------------------------------------------------------------------
// tf32 mma.sync GEMM (identical to R13/R15 — proven)
// ---------------------------------------------------------------------------
#define MG_STAGE  16384        // A(8K) + B(8K)

__device__ __forceinline__ void load_stage(uint32_t sstage,
        const float* __restrict__ A, const float* __restrict__ B,
        int arow0, int brow0, int K, int kc, int tid)
{
#pragma unroll
    for (int it = 0; it < 2; it++) {
        const int idx = tid + 256 * it;      // 0..511
        const int rr  = idx >> 2;            // row 0..127
        const int c4  = idx & 3;             // 16B chunk
        const uint32_t soff = rr * 64 + ((c4 ^ ((rr >> 1) & 3)) << 4);
        cpa16(sstage +        soff, A + (size_t)(arow0 + rr) * K + kc + c4 * 4);
        cpa16(sstage + 8192 + soff, B + (size_t)(brow0 + rr) * K + kc + c4 * 4);
    }
}

template<int EPI>   // 0: bias, 1: bias + softplus
__global__ __launch_bounds__(256, 2)
void mmagemm(const float* __restrict__ A, const float* __restrict__ B,
             const float* __restrict__ bias0, const float* __restrict__ bias1,
             float* __restrict__ C0, float* __restrict__ C1,
             int Nout, int Nsplit, int K)
{
    __shared__ char smem[3 * MG_STAGE];     // 48 KB static
    const uint32_t sb = smem_u32(smem);
    const int tid  = threadIdx.x;
    const int wid  = tid >> 5;
    const int lane = tid & 31;
    const int warp_m = wid & 1;
    const int warp_n = wid >> 1;
    const int arow0 = blockIdx.y * 128;
    const int brow0 = blockIdx.x * 128;

    const int rA = lane >> 2;                 // 0..7
    const int cA = lane & 3;                  // 0..3
    const int swz = ((rA >> 1) & 3) << 2;
    uint32_t kx[2], kx4[2];
#pragma unroll
    for (int s = 0; s < 2; s++) {
        kx[s]  = (uint32_t)(((s * 8 + cA)     ^ swz) << 2);
        kx4[s] = (uint32_t)(((s * 8 + cA + 4) ^ swz) << 2);
    }
    const int m0 = warp_m * 64;
    const int n0 = warp_n * 32;

    float acc[4][4][4];
#pragma unroll
    for (int a = 0; a < 4; a++)
#pragma unroll
        for (int b = 0; b < 4; b++)
#pragma unroll
            for (int c = 0; c < 4; c++) acc[a][b][c] = 0.f;

    const int nch = K >> 4;

    load_stage(sb,            A, B, arow0, brow0, K, 0,  tid);
    asm volatile("cp.async.commit_group;");
    load_stage(sb + MG_STAGE, A, B, arow0, brow0, K, 16, tid);
    asm volatile("cp.async.commit_group;");

    int stage = 0;
    for (int i = 0; i < nch; i++) {
        if (i + 1 < nch) {
            asm volatile("cp.async.wait_group 1;");
        } else {
            asm volatile("cp.async.wait_group 0;");
        }
        __syncthreads();

        if (i + 2 < nch) {
            int ns = stage + 2; if (ns >= 3) ns -= 3;
            load_stage(sb + ns * MG_STAGE, A, B, arow0, brow0, K, (i + 2) * 16, tid);
            asm volatile("cp.async.commit_group;");
        }

        const uint32_t st = sb + stage * MG_STAGE;
#pragma unroll
        for (int ks = 0; ks < 2; ks++) {
            uint32_t bf[4][2];
#pragma unroll
            for (int nt = 0; nt < 4; nt++) {
                const uint32_t rb = st + 8192 + (n0 + nt * 8 + rA) * 64;
                bf[nt][0] = lds32(rb + kx[ks]);
                bf[nt][1] = lds32(rb + kx4[ks]);
            }
#pragma unroll
            for (int mt = 0; mt < 4; mt++) {
                const uint32_t ra = st + (m0 + mt * 16 + rA) * 64;
                uint32_t af[4];
                af[0] = lds32(ra +       kx[ks]);
                af[1] = lds32(ra + 512 + kx[ks]);
                af[2] = lds32(ra +       kx4[ks]);
                af[3] = lds32(ra + 512 + kx4[ks]);
#pragma unroll
                for (int nt = 0; nt < 4; nt++)
                    mma_tf32(acc[mt][nt], af, bf[nt][0], bf[nt][1]);
            }
        }
        if (++stage == 3) stage = 0;
    }

    const float* bias = bias0;
    float* Cp = C0;
    int colbase = brow0;
    if (brow0 >= Nsplit) { bias = bias1; Cp = C1; colbase = brow0 - Nsplit; }

    const int gid = lane >> 2, tig = lane & 3;
#pragma unroll
    for (int mt = 0; mt < 4; mt++) {
        const int r0 = arow0 + m0 + mt * 16 + gid;
#pragma unroll
        for (int nt = 0; nt < 4; nt++) {
            const int col = colbase + n0 + nt * 8 + tig * 2;
            const float bb0 = __ldg(bias + col);
            const float bb1 = __ldg(bias + col + 1);
            float v0 = acc[mt][nt][0] + bb0;
            float v1 = acc[mt][nt][1] + bb1;
            float v2 = acc[mt][nt][2] + bb0;
            float v3 = acc[mt][nt][3] + bb1;
            if (EPI == 1) {
                v0 = (v0 > 20.f) ? v0 : log1pf(expf(v0));
                v1 = (v1 > 20.f) ? v1 : log1pf(expf(v1));
                v2 = (v2 > 20.f) ? v2 : log1pf(expf(v2));
                v3 = (v3 > 20.f) ? v3 : log1pf(expf(v3));
            }
            float2 p01; p01.x = v0; p01.y = v1;
            float2 p23; p23.x = v2; p23.y = v3;
            *(float2*)(Cp + (size_t)r0 * Nout + col)       = p01;
            *(float2*)(Cp + (size_t)(r0 + 8) * Nout + col) = p23;
        }
    }
}

// ---------------------------------------------------------------------------
// Prep kernel: x->tf32 round PLUS all 4 weight transposes, one launch.
// Block ranges: [0,4096) round, then in/gate/delta/out transpose tiles.
// ---------------------------------------------------------------------------
__device__ __forceinline__ void tr_tile(const float* __restrict__ W, int K, int N,
                                        float* __restrict__ T, int nt, int kt,
                                        int tid)
{
    __shared__ float ts[32][33];
    const int n0 = nt * 32, k0 = kt * 32;
    const int tx = tid & 31, ty = tid >> 5;
#pragma unroll
    for (int i = 0; i < 4; i++)
        ts[ty + i * 8][tx] = W[(size_t)(k0 + ty + i * 8) * N + n0 + tx];
    __syncthreads();
#pragma unroll
    for (int i = 0; i < 4; i++)
        T[(size_t)(n0 + ty + i * 8) * K + k0 + tx] = to_tf32(ts[tx][ty + i * 8]);
}

#define NB_ROUND 4096      // (MTOT*DMODEL/4)/256
#define NB_IN    2048      // 64 x 32 tiles
#define NB_GATE  2048
#define NB_DELTA 4096      // 64 x 64
#define NB_OUT   2048      // 32 x 64
#define NB_PREP  (NB_ROUND + NB_IN + NB_GATE + NB_DELTA + NB_OUT)

__global__ __launch_bounds__(256)
void prep_kernel(const float* __restrict__ x,
                 const float* __restrict__ W_in, const float* __restrict__ W_gate,
                 const float* __restrict__ W_delta, const float* __restrict__ W_out,
                 float* __restrict__ xt, float* __restrict__ wt_ing,
                 float* __restrict__ wtd, float* __restrict__ wto)
{
    const int tid = threadIdx.x;
    int b = blockIdx.x;
    if (b < NB_ROUND) {
        const int i = b * 256 + tid;
        float4 v = ((const float4*)x)[i];
        v.x = to_tf32(v.x); v.y = to_tf32(v.y);
        v.z = to_tf32(v.z); v.w = to_tf32(v.w);
        ((float4*)xt)[i] = v;
        return;
    }
    b -= NB_ROUND;
    if (b < NB_IN) {
        tr_tile(W_in, DMODEL, DINNER, wt_ing, b & 63, b >> 6, tid);
        return;
    }
    b -= NB_IN;
    if (b < NB_GATE) {
        tr_tile(W_gate, DMODEL, DINNER, wt_ing + (size_t)DINNER * DMODEL,
                b & 63, b >> 6, tid);
        return;
    }
    b -= NB_GATE;
    if (b < NB_DELTA) {
        tr_tile(W_delta, DINNER, DINNER, wtd, b & 63, b >> 6, tid);
        return;
    }
    b -= NB_DELTA;
    tr_tile(W_out, DINNER, DMODEL, wto, b & 31, b >> 5, tid);
}

// ---------------------------------------------------------------------------
// Causal depthwise conv (K=4) + bias + silu, float4 over channels.
// Same per-element arithmetic order as scalar version.
// ---------------------------------------------------------------------------
__global__ __launch_bounds__(256)
void conv_silu(const float* __restrict__ xz, const float* __restrict__ w,
               const float* __restrict__ cb, float* __restrict__ act,
               float* __restrict__ act_t)
{
    const int i4 = blockIdx.x * 256 + threadIdx.x;   // over MTOT*DINNER/4
    if (i4 >= MTOT * DINNER / 4) return;
    const int idx = i4 * 4;
    const int d = idx & (DINNER - 1);                // multiple of 4
    const int bt = idx >> 11;
    const int t = bt & (LSEQ - 1);

    // weights for 4 channels: wv[j] = w[(d+j)*4 + 0..3]
    float4 wv0 = *(const float4*)(w + (d + 0) * KCONV);
    float4 wv1 = *(const float4*)(w + (d + 1) * KCONV);
    float4 wv2 = *(const float4*)(w + (d + 2) * KCONV);
    float4 wv3 = *(const float4*)(w + (d + 3) * KCONV);
    float4 s = *(const float4*)(cb + d);

#pragma unroll
    for (int k = 0; k < KCONV; k++) {
        const int tt = t - (KCONV - 1) + k;
        if (tt >= 0) {
            const float4 v = *(const float4*)(xz + idx + (k - (KCONV - 1)) * DINNER);
            const float w0 = (k == 0) ? wv0.x : (k == 1) ? wv0.y : (k == 2) ? wv0.z : wv0.w;
            const float w1 = (k == 0) ? wv1.x : (k == 1) ? wv1.y : (k == 2) ? wv1.z : wv1.w;
            const float w2 = (k == 0) ? wv2.x : (k == 1) ? wv2.y : (k == 2) ? wv2.z : wv2.w;
            const float w3 = (k == 0) ? wv3.x : (k == 1) ? wv3.y : (k == 2) ? wv3.z : wv3.w;
            s.x = fmaf(w0, v.x, s.x);
            s.y = fmaf(w1, v.y, s.y);
            s.z = fmaf(w2, v.z, s.z);
            s.w = fmaf(w3, v.w, s.w);
        }
    }
    float4 a4, t4;
    a4.x = s.x / (1.f + __expf(-s.x));
    a4.y = s.y / (1.f + __expf(-s.y));
    a4.z = s.z / (1.f + __expf(-s.z));
    a4.w = s.w / (1.f + __expf(-s.w));
    t4.x = to_tf32(a4.x); t4.y = to_tf32(a4.y);
    t4.z = to_tf32(a4.z); t4.w = to_tf32(a4.w);
    *(float4*)(act + idx)   = a4;
    *(float4*)(act_t + idx) = t4;
}

// ---------------------------------------------------------------------------
// Skinny GEMM: Bm = act @ W_B, Cm = act @ W_C  — float4 n-quads.
// One thread per (m, n-quad); k ascending, single accumulator per (m,n)
// -> bitwise-identical to the scalar version.
// ---------------------------------------------------------------------------
__global__ __launch_bounds__(256)
void bc_gemm(const float* __restrict__ act,
             const float* __restrict__ WB, const float* __restrict__ WC,
             float* __restrict__ Bm, float* __restrict__ Cm)
{
    const int g = blockIdx.x * 256 + threadIdx.x;   // 0..16383
    const int m = g >> 2;
    const int q = (g & 3) * 4;
    const float* a = act + (size_t)m * DINNER;

    float4 sb = make_float4(0.f, 0.f, 0.f, 0.f);
    float4 sc = make_float4(0.f, 0.f, 0.f, 0.f);
#pragma unroll 8
    for (int k = 0; k < DINNER; k++) {
        const float av = a[k];
        const float4 wb = *(const float4*)(WB + k * NSTATE + q);
        const float4 wc = *(const float4*)(WC + k * NSTATE + q);
        sb.x = fmaf(av, wb.x, sb.x);
        sb.y = fmaf(av, wb.y, sb.y);
        sb.z = fmaf(av, wb.z, sb.z);
        sb.w = fmaf(av, wb.w, sb.w);
        sc.x = fmaf(av, wc.x, sc.x);
        sc.y = fmaf(av, wc.y, sc.y);
        sc.z = fmaf(av, wc.z, sc.z);
        sc.w = fmaf(av, wc.w, sc.w);
    }
    *(float4*)(Bm + m * NSTATE + q) = sb;
    *(float4*)(Cm + m * NSTATE + q) = sc;
}

// ---------------------------------------------------------------------------
// Selective scan + skip + gating (R15 structure — proven).
// ---------------------------------------------------------------------------
__global__ __launch_bounds__(256)
void scan_kernel(const float* __restrict__ delta, const float* __restrict__ act,
                 const float* __restrict__ Bm, const float* __restrict__ Cm,
                 const float* __restrict__ A_log, const float* __restrict__ D_skip,
                 const float* __restrict__ xg, float* __restrict__ gt)
{
    const int w = blockIdx.x * 8 + (threadIdx.x >> 5);   // 0 .. 2047
    const int lane = threadIdx.x & 31;
    const int n = lane & 15;
    const int b = w >> 10;
    const int dp = w & 1023;
    const int d = dp * 2 + (lane >> 4);

    const float a = -expf(A_log[d * NSTATE + n]);
    const float dsk = D_skip[d];

    const float* pD = delta + (size_t)b * LSEQ * DINNER + d;
    const float* pX = act   + (size_t)b * LSEQ * DINNER + d;
    const float* pG = xg    + (size_t)b * LSEQ * DINNER + d;
    float*       pT = gt    + (size_t)b * LSEQ * DINNER + d;
    const float* pB = Bm + (size_t)b * LSEQ * NSTATE + n;
    const float* pC = Cm + (size_t)b * LSEQ * NSTATE + n;

    float h = 0.f;
    for (int t0 = 0; t0 < LSEQ; t0 += 8) {
        float dv[8], xv[8], gv[8], bv[8], cv[8];
#pragma unroll
        for (int jj = 0; jj < 8; jj++) {
            const size_t o = (size_t)(t0 + jj) * DINNER;
            dv[jj] = pD[o];
            xv[jj] = pX[o];
            gv[jj] = pG[o];
            bv[jj] = pB[(t0 + jj) * NSTATE];
            cv[jj] = pC[(t0 + jj) * NSTATE];
        }
        float dA[8];
#pragma unroll
        for (int jj = 0; jj < 8; jj++) dA[jj] = __expf(dv[jj] * a);
        float p[8];
#pragma unroll
        for (int jj = 0; jj < 8; jj++) {
            h = fmaf(dA[jj], h, (dv[jj] * xv[jj]) * bv[jj]);
            p[jj] = h * cv[jj];
        }
#pragma unroll
        for (int s = 1; s <= 8; s <<= 1) {
#pragma unroll
            for (int jj = 0; jj < 8; jj++)
                p[jj] += __shfl_xor_sync(0xffffffffu, p[jj], s);
        }
        if (n == 0) {
#pragma unroll
            for (int jj = 0; jj < 8; jj++) {
                const float g = gv[jj];
                const float y = (p[jj] + xv[jj] * dsk) * (g / (1.f + __expf(-g)));
                pT[(size_t)(t0 + jj) * DINNER] = to_tf32(y);
            }
        }
    }
}

// ---------------------------------------------------------------------------
// Launch
// ---------------------------------------------------------------------------
extern "C" void kernel_launch(void* const* d_in, const int* in_sizes, int n_in,
                              void* d_out, int out_size)
{
    const float* x      = (const float*)d_in[0];
    const float* W_in   = (const float*)d_in[1];
    const float* b_in   = (const float*)d_in[2];
    const float* W_gate = (const float*)d_in[3];
    const float* b_gate = (const float*)d_in[4];
    const float* conv_w = (const float*)d_in[5];
    const float* conv_b = (const float*)d_in[6];
    const float* A_log  = (const float*)d_in[7];
    const float* D_skip = (const float*)d_in[8];
    const float* W_delta= (const float*)d_in[9];
    const float* b_delta= (const float*)d_in[10];
    const float* W_B    = (const float*)d_in[11];
    const float* W_C    = (const float*)d_in[12];
    const float* W_out  = (const float*)d_in[13];
    const float* b_out  = (const float*)d_in[14];
    float* out = (float*)d_out;

    float *xz, *xg, *act, *delt, *Bm, *Cm, *xt, *at, *gt, *wt_ing, *wtd, *wto;
    cudaGetSymbolAddress((void**)&xz,     g_xz);
    cudaGetSymbolAddress((void**)&xg,     g_xg);
    cudaGetSymbolAddress((void**)&act,    g_act);
    cudaGetSymbolAddress((void**)&delt,   g_delta);
    cudaGetSymbolAddress((void**)&Bm,     g_Bm);
    cudaGetSymbolAddress((void**)&Cm,     g_Cm);
    cudaGetSymbolAddress((void**)&xt,     g_xt);
    cudaGetSymbolAddress((void**)&at,     g_at);
    cudaGetSymbolAddress((void**)&gt,     g_gt);
    cudaGetSymbolAddress((void**)&wt_ing, g_wt_ing);
    cudaGetSymbolAddress((void**)&wtd,    g_wtd);
    cudaGetSymbolAddress((void**)&wto,    g_wto);

    // 0) one prep launch: round x + transpose/round all 4 weight matrices
    prep_kernel<<<NB_PREP, 256>>>(x, W_in, W_gate, W_delta, W_out,
                                  xt, wt_ing, wtd, wto);
    // 1) fused in+gate: [xz | xg] = x @ [W_in | W_gate] + [b_in | b_gate]
    {
        dim3 grid(2 * DINNER / 128, MTOT / 128);     // 32 x 32
        mmagemm<0><<<grid, 256>>>(xt, wt_ing, b_in, b_gate,
                                  xz, xg, DINNER, DINNER, DMODEL);
    }
    // 2) act = silu(conv(xz) + conv_b)  (+ tf32 copy)
    {
        const int n4 = MTOT * DINNER / 4;
        conv_silu<<<(n4 + 255) / 256, 256>>>(xz, conv_w, conv_b, act, at);
    }
    // 3) delta = softplus(act @ W_delta + b_delta)
    {
        dim3 grid(DINNER / 128, MTOT / 128);
        mmagemm<1><<<grid, 256>>>(at, wtd, b_delta, b_delta,
                                  delt, delt, DINNER, DINNER, DINNER);
    }
    // 4) Bm, Cm
    {
        bc_gemm<<<MTOT * 4 / 256, 256>>>(act, W_B, W_C, Bm, Cm);
    }
    // 5) scan + skip + gating -> gt (tf32-rounded)
    {
        scan_kernel<<<(BATCH * DINNER / 2) / 8, 256>>>(delt, act, Bm, Cm,
                                                       A_log, D_skip, xg, gt);
    }
    // 6) out = gated @ W_out + b_out
    {
        dim3 grid(DMODEL / 128, MTOT / 128);
        mmagemm<0><<<grid, 256>>>(gt, wto, b_out, b_out,
                                  out, out, DMODEL, DMODEL, DINNER);
    }
}